// round 1
// baseline (speedup 1.0000x reference)
#include <cuda_runtime.h>
#include <math.h>

// Problem constants (fixed shapes: B=16, T=512, D=512)
constexpr int Bn = 16;
constexpr int Tn = 512;
constexpr int Dn = 512;
constexpr int BT = Bn * Tn;              // 8192 (b,t) rows
constexpr int MAXTOT = BT + 2 * Bn;      // 8224 max bank rows
constexpr int TOTPAD = 8320;             // 65*128, padded so N-tiles never read OOB
constexpr int MTILE = 128;
constexpr int NTILE = 128;
constexpr int KCH = 16;
constexpr int NCHUNKS = 4;
constexpr int CHUNK_COLS = 17 * 128;     // 2176; 4*2176 = 8704 >= 8224
constexpr int RT = BT / MTILE;           // 64 row tiles (worst case)

// ---- device-side scratch (no allocations allowed) ----
__device__ float g_bank[TOTPAD * Dn];    // zero-padded feature bank [total, D]
__device__ int   g_src[TOTPAD];          // bank row -> feats row index (b*T+t) or -1 (sentinel/unused)
__device__ int   g_rowhid[BT];           // packed valid row -> hidden row index (b*T+t)
__device__ int   g_dest[BT];             // packed valid row -> bank row it was scattered to
__device__ int   g_rowbatch[BT];         // packed valid row -> b
__device__ int   g_S;                    // number of valid rows = sum(L)
__device__ int   g_total;                // S + 2*B
__device__ float g_invL[Bn];
__device__ float g_pm[2 * NCHUNKS * BT]; // partial running max  per (dir, chunk, row)
__device__ float g_ps[2 * NCHUNKS * BT]; // partial running sumexp
__device__ float g_lse[2 * BT];
__device__ float g_diag[2 * BT];

// ------------------------------------------------------------------
// 1) layout setup (single block)
// ------------------------------------------------------------------
__global__ void setup_kernel(const int* __restrict__ seq_lens) {
    __shared__ int sL[Bn], sCum[Bn + 1], sStart[Bn];
    int tid = threadIdx.x;
    if (tid == 0) {
        int c = 0;
        for (int i = 0; i < Bn; i++) {
            sL[i] = seq_lens[i];
            sCum[i] = c;
            sStart[i] = 2 * i + c;
            c += sL[i];
        }
        sCum[Bn] = c;
        g_S = c;
        g_total = c + 2 * Bn;
    }
    __syncthreads();
    int S = sCum[Bn];
    int total = S + 2 * Bn;
    if (tid < Bn) g_invL[tid] = 1.0f / (float)sL[tid];

    // bank row -> source feats row (-1 for sentinels / unused / padding)
    for (int r = tid; r < TOTPAD; r += blockDim.x) {
        int src = -1;
        if (r < total) {
            for (int i = 0; i < Bn; i++) {
                int s0 = sStart[i];
                if (r >= s0 && r < s0 + sL[i] + 2) {
                    if (r > s0 && r < s0 + sL[i] + 1) src = i * Tn + (r - s0 - 1);
                    break;
                }
            }
        }
        g_src[r] = src;
    }
    // packed valid-row metadata
    for (int r = tid; r < BT; r += blockDim.x) {
        if (r < S) {
            int b = 0;
            for (int i = 0; i < Bn; i++) {
                if (r >= sCum[i] && r < sCum[i + 1]) { b = i; break; }
            }
            int t = r - sCum[b];
            g_rowhid[r]   = b * Tn + t;
            g_dest[r]     = sStart[b] + 1 + t;
            g_rowbatch[r] = b;
        } else {
            g_rowhid[r] = 0; g_dest[r] = 1; g_rowbatch[r] = 0;
        }
    }
}

// ------------------------------------------------------------------
// 2) build the bank: zero sentinels + padding, scatter feats
//    grid = TOTPAD blocks, 128 threads (one float4 each -> 512 floats/row)
// ------------------------------------------------------------------
__global__ void bank_kernel(const float* __restrict__ feats) {
    int row = blockIdx.x;
    int src = g_src[row];
    float4 v = make_float4(0.f, 0.f, 0.f, 0.f);
    if (src >= 0) v = reinterpret_cast<const float4*>(feats)[src * (Dn / 4) + threadIdx.x];
    reinterpret_cast<float4*>(g_bank)[row * (Dn / 4) + threadIdx.x] = v;
}

// ------------------------------------------------------------------
// 3) diagonal logits: one warp per (valid row, dir)
//    grid = (BT/8, 2), block 256 (8 warps)
// ------------------------------------------------------------------
__global__ void diag_kernel(const float* __restrict__ hidden) {
    int r = blockIdx.x * 8 + (threadIdx.x >> 5);
    if (r >= g_S) return;
    int dir  = blockIdx.y;
    int lane = threadIdx.x & 31;
    int hrow = g_rowhid[r];
    int col  = g_dest[r] + (dir == 0 ? 1 : -1);
    const float4* h = reinterpret_cast<const float4*>(hidden + hrow * (2 * Dn) + dir * Dn);
    const float4* x = reinterpret_cast<const float4*>(g_bank + (size_t)col * Dn);
    float sum = 0.f;
#pragma unroll
    for (int j = 0; j < 4; j++) {
        float4 a = h[lane + j * 32];
        float4 b = x[lane + j * 32];
        sum += a.x * b.x + a.y * b.y + a.z * b.z + a.w * b.w;
    }
#pragma unroll
    for (int o = 16; o >= 1; o >>= 1) sum += __shfl_xor_sync(0xffffffffu, sum, o);
    if (lane == 0) g_diag[dir * BT + r] = sum;
}

// ------------------------------------------------------------------
// 4) main fused GEMM + online log-sum-exp
//    grid = (RT, NCHUNKS, 2), block 256
//    thread (ty,tx) in 16x16 grid: rows ty*8..+7, cols tx*8..+7 of a 128x128 tile
// ------------------------------------------------------------------
__global__ void __launch_bounds__(256, 2) lse_kernel(const float* __restrict__ hidden) {
    const int dir   = blockIdx.z;
    const int chunk = blockIdx.y;
    const int m0    = blockIdx.x * MTILE;
    const int S     = g_S;
    const int total = g_total;
    const int nbeg  = chunk * CHUNK_COLS;
    const int nend  = min(nbeg + CHUNK_COLS, total);

    __shared__ float As[KCH][MTILE + 4];
    __shared__ float Bs[KCH][NTILE + 4];
    __shared__ int   rowbase[MTILE];

    const int tid = threadIdx.x;
    const int tx = tid & 15, ty = tid >> 4;

    if (tid < MTILE) {
        int m = m0 + tid;
        int rh = g_rowhid[min(m, S - 1)];
        rowbase[tid] = rh * (2 * Dn) + dir * Dn;
    }
    __syncthreads();

    float mrun[8], srun[8];
#pragma unroll
    for (int i = 0; i < 8; i++) { mrun[i] = -INFINITY; srun[i] = 0.f; }

    if (m0 < S && nbeg < total) {
        const int r    = tid >> 1;          // 0..127
        const int half = tid & 1;           // which 8-float piece of the 16-float K chunk
        const int kk0  = half * 8;

        for (int n0 = nbeg; n0 < nend; n0 += NTILE) {
            float acc[8][8];
#pragma unroll
            for (int i = 0; i < 8; i++)
#pragma unroll
                for (int j = 0; j < 8; j++) acc[i][j] = 0.f;

            for (int k0 = 0; k0 < Dn; k0 += KCH) {
                // -- load A chunk (gathered hidden rows), store K-major transposed
                {
                    const float* src = hidden + rowbase[r] + k0 + kk0;
                    float4 v0 = reinterpret_cast<const float4*>(src)[0];
                    float4 v1 = reinterpret_cast<const float4*>(src)[1];
                    As[kk0 + 0][r] = v0.x; As[kk0 + 1][r] = v0.y;
                    As[kk0 + 2][r] = v0.z; As[kk0 + 3][r] = v0.w;
                    As[kk0 + 4][r] = v1.x; As[kk0 + 5][r] = v1.y;
                    As[kk0 + 6][r] = v1.z; As[kk0 + 7][r] = v1.w;
                }
                // -- load B chunk (contiguous bank rows); n0+r < TOTPAD by construction
                {
                    const float* src = g_bank + (size_t)(n0 + r) * Dn + k0 + kk0;
                    float4 v0 = reinterpret_cast<const float4*>(src)[0];
                    float4 v1 = reinterpret_cast<const float4*>(src)[1];
                    Bs[kk0 + 0][r] = v0.x; Bs[kk0 + 1][r] = v0.y;
                    Bs[kk0 + 2][r] = v0.z; Bs[kk0 + 3][r] = v0.w;
                    Bs[kk0 + 4][r] = v1.x; Bs[kk0 + 5][r] = v1.y;
                    Bs[kk0 + 6][r] = v1.z; Bs[kk0 + 7][r] = v1.w;
                }
                __syncthreads();
#pragma unroll
                for (int kk = 0; kk < KCH; kk++) {
                    float4 a0 = *reinterpret_cast<const float4*>(&As[kk][ty * 8]);
                    float4 a1 = *reinterpret_cast<const float4*>(&As[kk][ty * 8 + 4]);
                    float4 b0 = *reinterpret_cast<const float4*>(&Bs[kk][tx * 8]);
                    float4 b1 = *reinterpret_cast<const float4*>(&Bs[kk][tx * 8 + 4]);
                    float a[8] = {a0.x, a0.y, a0.z, a0.w, a1.x, a1.y, a1.z, a1.w};
                    float b[8] = {b0.x, b0.y, b0.z, b0.w, b1.x, b1.y, b1.z, b1.w};
#pragma unroll
                    for (int i = 0; i < 8; i++)
#pragma unroll
                        for (int j = 0; j < 8; j++) acc[i][j] = fmaf(a[i], b[j], acc[i][j]);
                }
                __syncthreads();
            }

            // -- fold this 128-col tile into the running (max, sumexp) per row
            const int cbase = n0 + tx * 8;
            bool valid[8];
#pragma unroll
            for (int j = 0; j < 8; j++) valid[j] = (cbase + j) < nend;
#pragma unroll
            for (int i = 0; i < 8; i++) {
                float tmax = -INFINITY;
#pragma unroll
                for (int j = 0; j < 8; j++) if (valid[j]) tmax = fmaxf(tmax, acc[i][j]);
#pragma unroll
                for (int o = 8; o >= 1; o >>= 1)
                    tmax = fmaxf(tmax, __shfl_xor_sync(0xffffffffu, tmax, o));
                float nm = fmaxf(mrun[i], tmax);
                float p = 0.f;
#pragma unroll
                for (int j = 0; j < 8; j++) if (valid[j]) p += __expf(acc[i][j] - nm);
#pragma unroll
                for (int o = 8; o >= 1; o >>= 1)
                    p += __shfl_xor_sync(0xffffffffu, p, o);
                float scale = __expf(fmaxf(mrun[i] - nm, -88.f)); // -inf -> clamp; srun=0 anyway
                srun[i] = srun[i] * scale + p;
                mrun[i] = nm;
            }
        }
    }

    // every block writes its partials (inactive -> (-inf, 0), combine skips)
    if (tx == 0) {
        int base = (dir * NCHUNKS + chunk) * BT;
#pragma unroll
        for (int i = 0; i < 8; i++) {
            int m = m0 + ty * 8 + i;
            g_pm[base + m] = mrun[i];
            g_ps[base + m] = srun[i];
        }
    }
}

// ------------------------------------------------------------------
// 5) combine N-chunk partials into lse per row
// ------------------------------------------------------------------
__global__ void combine_kernel() {
    int idx = blockIdx.x * blockDim.x + threadIdx.x;
    if (idx >= 2 * BT) return;
    int dir = idx / BT, r = idx % BT;
    if (r >= g_S) return;
    float M = -INFINITY;
#pragma unroll
    for (int c = 0; c < NCHUNKS; c++)
        M = fmaxf(M, g_pm[(dir * NCHUNKS + c) * BT + r]);
    float s = 0.f;
#pragma unroll
    for (int c = 0; c < NCHUNKS; c++) {
        float mm = g_pm[(dir * NCHUNKS + c) * BT + r];
        float ss = g_ps[(dir * NCHUNKS + c) * BT + r];
        if (ss > 0.f) s += ss * __expf(mm - M);
    }
    g_lse[dir * BT + r] = M + logf(s);
}

// ------------------------------------------------------------------
// 6) final reduction -> out[0]=fw_loss, out[1]=bw_loss
// ------------------------------------------------------------------
__global__ void reduce_kernel(float* __restrict__ out) {
    __shared__ double sh[256][2];
    int tid = threadIdx.x;
    int S = g_S;
    double a0 = 0.0, a1 = 0.0;
    for (int r = tid; r < S; r += 256) {
        double w = (double)g_invL[g_rowbatch[r]];
        a0 += (double)(g_lse[r]        - g_diag[r])        * w;
        a1 += (double)(g_lse[BT + r]   - g_diag[BT + r])   * w;
    }
    sh[tid][0] = a0; sh[tid][1] = a1;
    __syncthreads();
    for (int o = 128; o >= 1; o >>= 1) {
        if (tid < o) { sh[tid][0] += sh[tid + o][0]; sh[tid][1] += sh[tid + o][1]; }
        __syncthreads();
    }
    if (tid == 0) {
        out[0] = (float)(sh[0][0] / (double)Bn);
        out[1] = (float)(sh[0][1] / (double)Bn);
    }
}

// ------------------------------------------------------------------
extern "C" void kernel_launch(void* const* d_in, const int* in_sizes, int n_in,
                              void* d_out, int out_size) {
    const float* feats    = (const float*)d_in[0];
    const float* hidden   = (const float*)d_in[1];
    const int*   seq_lens = (const int*)d_in[2];
    float* out = (float*)d_out;

    setup_kernel<<<1, 256>>>(seq_lens);
    bank_kernel<<<TOTPAD, 128>>>(feats);
    diag_kernel<<<dim3(BT / 8, 2), 256>>>(hidden);
    lse_kernel<<<dim3(RT, NCHUNKS, 2), 256>>>(hidden);
    combine_kernel<<<(2 * BT + 255) / 256, 256>>>();
    reduce_kernel<<<1, 256>>>(out);
    (void)in_sizes; (void)n_in; (void)out_size;
}

// round 4
// speedup vs baseline: 8.7936x; 8.7936x over previous
#include <cuda_runtime.h>
#include <cuda_bf16.h>
#include <math.h>
#include <stdint.h>

// ----- problem constants (B=16, T=512, D=512) -----
constexpr int Bn = 16;
constexpr int Tn = 512;
constexpr int Dn = 512;
constexpr int BT = Bn * Tn;            // 8192
constexpr int TOTPAD = 8320;           // 65*128 max bank rows (padded)
constexpr int NCHUNKS = 4;
constexpr int MT_MAX = 64;             // worst-case M tiles
constexpr int KC = 32;                 // K per chunk
constexpr int NKCH = Dn / KC;          // 16
constexpr int ASTRIDE = 520;           // bf16 per A smem row (1040 B, conflict-free)
constexpr int BSTRIDE = 40;            // bf16 per B smem row (80 B)
constexpr int BSTAGES = 5;
constexpr int A_BYTES = 128 * ASTRIDE * 2;      // 133120
constexpr int BSTG_BYTES = 128 * BSTRIDE * 2;   // 10240
constexpr int DYN_BYTES = A_BYTES + BSTAGES * BSTG_BYTES; // 184320

// ----- device scratch (no allocations allowed) -----
__device__ __nv_bfloat16 g_hidb[2 * BT * Dn];    // [dir][row][512]
__device__ __nv_bfloat16 g_bankb[TOTPAD * Dn];   // zero-padded bank, bf16
__device__ int   g_src[TOTPAD];
__device__ int   g_rowhid[BT];
__device__ int   g_rowbatch[BT];
__device__ int   g_L[Bn];
__device__ float g_invL[Bn];
__device__ int   g_S, g_total;
__device__ int   g_cbeg[NCHUNKS + 1];
__device__ float g_pm[2 * NCHUNKS * BT];
__device__ float g_ps[2 * NCHUNKS * BT];
__device__ float g_lse[2 * BT];
__device__ float g_diag[2 * BT];

// ----- helpers -----
__device__ __forceinline__ uint32_t smem_u32(const void* p) {
    uint32_t a;
    asm("{ .reg .u64 t; cvta.to.shared.u64 t, %1; cvt.u32.u64 %0, t; }" : "=r"(a) : "l"(p));
    return a;
}
__device__ __forceinline__ void cp16(uint32_t dst, const void* src) {
    asm volatile("cp.async.cg.shared.global [%0], [%1], 16;" :: "r"(dst), "l"(src) : "memory");
}
__device__ __forceinline__ void cp_commit() {
    asm volatile("cp.async.commit_group;" ::: "memory");
}
__device__ __forceinline__ void cp_wait0() {
    asm volatile("cp.async.wait_group 0;" ::: "memory");
}
__device__ __forceinline__ void cp_wait3() {
    asm volatile("cp.async.wait_group 3;" ::: "memory");
}
__device__ __forceinline__ void ldsm_x4(uint32_t& r0, uint32_t& r1, uint32_t& r2, uint32_t& r3, uint32_t a) {
    asm volatile("ldmatrix.sync.aligned.m8n8.x4.shared.b16 {%0,%1,%2,%3}, [%4];"
                 : "=r"(r0), "=r"(r1), "=r"(r2), "=r"(r3) : "r"(a));
}
__device__ __forceinline__ void ldsm_x4t(uint32_t& r0, uint32_t& r1, uint32_t& r2, uint32_t& r3, uint32_t a) {
    asm volatile("ldmatrix.sync.aligned.m8n8.x4.trans.shared.b16 {%0,%1,%2,%3}, [%4];"
                 : "=r"(r0), "=r"(r1), "=r"(r2), "=r"(r3) : "r"(a));
}
__device__ __forceinline__ void mma16816(float* c, const uint32_t* a, uint32_t b0, uint32_t b1) {
    asm volatile("mma.sync.aligned.m16n8k16.row.col.f32.bf16.bf16.f32 "
                 "{%0,%1,%2,%3}, {%4,%5,%6,%7}, {%8,%9}, {%0,%1,%2,%3};"
                 : "+f"(c[0]), "+f"(c[1]), "+f"(c[2]), "+f"(c[3])
                 : "r"(a[0]), "r"(a[1]), "r"(a[2]), "r"(a[3]), "r"(b0), "r"(b1));
}
__device__ __forceinline__ uint32_t f2bf2(float lo, float hi) {
    uint32_t r;
    asm("cvt.rn.bf16x2.f32 %0, %1, %2;" : "=r"(r) : "f"(hi), "f"(lo));
    return r;
}

// ------------------------------------------------------------------
// 1) layout setup (single block)
// ------------------------------------------------------------------
__global__ void setup_kernel(const int* __restrict__ seq_lens) {
    __shared__ int sL[Bn], sCum[Bn + 1], sStart[Bn];
    int tid = threadIdx.x;
    if (tid == 0) {
        int c = 0;
        for (int i = 0; i < Bn; i++) {
            sL[i] = seq_lens[i];
            sCum[i] = c;
            sStart[i] = 2 * i + c;
            c += sL[i];
        }
        sCum[Bn] = c;
        g_S = c;
        g_total = c + 2 * Bn;
        int ntiles = (g_total + 127) / 128;
        int q = ntiles / NCHUNKS, rem = ntiles % NCHUNKS, a = 0;
        g_cbeg[0] = 0;
        for (int i = 0; i < NCHUNKS; i++) {
            a += q + (i < rem ? 1 : 0);
            g_cbeg[i + 1] = a * 128;
        }
    }
    __syncthreads();
    int S = sCum[Bn];
    int total = S + 2 * Bn;
    if (tid < Bn) { g_invL[tid] = 1.0f / (float)sL[tid]; g_L[tid] = sL[tid]; }

    for (int r = tid; r < TOTPAD; r += blockDim.x) {
        int src = -1;
        if (r < total) {
            for (int i = 0; i < Bn; i++) {
                int s0 = sStart[i];
                if (r >= s0 && r < s0 + sL[i] + 2) {
                    if (r > s0 && r < s0 + sL[i] + 1) src = i * Tn + (r - s0 - 1);
                    break;
                }
            }
        }
        g_src[r] = src;
    }
    for (int r = tid; r < BT; r += blockDim.x) {
        if (r < S) {
            int b = 0;
            for (int i = 0; i < Bn; i++)
                if (r >= sCum[i] && r < sCum[i + 1]) { b = i; break; }
            int t = r - sCum[b];
            g_rowhid[r] = b * Tn + t;
            g_rowbatch[r] = b;
        } else {
            g_rowhid[r] = 0; g_rowbatch[r] = 0;
        }
    }
}

// ------------------------------------------------------------------
// 2a) hidden fp32 -> bf16 split per direction
// ------------------------------------------------------------------
__global__ void hidcvt_kernel(const float* __restrict__ hidden) {
    int row = blockIdx.x;
    int tid = threadIdx.x;                  // 0..255, 4 floats each
    float4 v = reinterpret_cast<const float4*>(hidden)[row * 256 + tid];
    int dir = tid >= 128;
    int col = tid * 4 - dir * 512;
    uint2 o = make_uint2(f2bf2(v.x, v.y), f2bf2(v.z, v.w));
    *reinterpret_cast<uint2*>(&g_hidb[((size_t)dir * BT + row) * Dn + col]) = o;
}

// ------------------------------------------------------------------
// 2b) feats -> zero-padded bf16 bank
// ------------------------------------------------------------------
__global__ void bankcvt_kernel(const float* __restrict__ feats) {
    int row = blockIdx.x;
    int tid = threadIdx.x;                  // 0..127
    int src = g_src[row];
    float4 v = make_float4(0.f, 0.f, 0.f, 0.f);
    if (src >= 0) v = reinterpret_cast<const float4*>(feats)[src * 128 + tid];
    uint2 o = make_uint2(f2bf2(v.x, v.y), f2bf2(v.z, v.w));
    *reinterpret_cast<uint2*>(&g_bankb[(size_t)row * Dn + tid * 4]) = o;
}

// ------------------------------------------------------------------
// 3) exact fp32 diagonal logits
// ------------------------------------------------------------------
__global__ void diag_kernel(const float* __restrict__ hidden,
                            const float* __restrict__ feats) {
    int r = blockIdx.x * 8 + (threadIdx.x >> 5);
    if (r >= g_S) return;
    int dir = blockIdx.y;
    int lane = threadIdx.x & 31;
    int hrow = g_rowhid[r];
    int b = hrow >> 9, t = hrow & 511;
    bool ok = dir == 0 ? (t + 1 < g_L[b]) : (t > 0);
    float sum = 0.f;
    if (ok) {
        int frow = hrow + (dir == 0 ? 1 : -1);
        const float4* h = reinterpret_cast<const float4*>(hidden + (size_t)hrow * 1024 + dir * Dn);
        const float4* x = reinterpret_cast<const float4*>(feats + (size_t)frow * Dn);
#pragma unroll
        for (int j = 0; j < 4; j++) {
            float4 a = h[lane + j * 32];
            float4 c = x[lane + j * 32];
            sum += a.x * c.x + a.y * c.y + a.z * c.z + a.w * c.w;
        }
#pragma unroll
        for (int o = 16; o >= 1; o >>= 1) sum += __shfl_xor_sync(0xffffffffu, sum, o);
    }
    if (lane == 0) g_diag[dir * BT + r] = sum;
}

// ------------------------------------------------------------------
// 4) mma.sync bf16 GEMM + online log-sum-exp
//    grid (MT_MAX, NCHUNKS, 2), 256 threads, warp tile 16x128
// ------------------------------------------------------------------
__global__ void __launch_bounds__(256, 1) lse_kernel() {
    extern __shared__ char dyn[];
    __shared__ int s_rows[128];

    const int S = g_S;
    const int m0 = blockIdx.x * 128;
    if (m0 >= S) return;
    const int chunk = blockIdx.y;
    const int dir = blockIdx.z;
    const int nbeg = g_cbeg[chunk];
    const int nend = min(g_cbeg[chunk + 1], g_total);
    const int tiles = nbeg < nend ? (nend - nbeg + 127) >> 7 : 0;

    const int tid = threadIdx.x;
    const int warp = tid >> 5;
    const int lane = tid & 31;
    const uint32_t sA = smem_u32(dyn);
    const uint32_t sB = sA + A_BYTES;

    if (tid < 128) s_rows[tid] = g_rowhid[min(m0 + tid, S - 1)];
    __syncthreads();

    // ---- load full-K A tile (gathered hidden rows) via cp.async ----
    const __nv_bfloat16* hb = g_hidb + (size_t)dir * BT * Dn;
    for (int u = tid; u < 128 * 64; u += 256) {   // 128 rows x 64 16B-segs
        int r = u >> 6, seg = u & 63;
        cp16(sA + r * (ASTRIDE * 2) + seg * 16, hb + (size_t)s_rows[r] * Dn + seg * 8);
    }
    cp_commit();
    cp_wait0();
    __syncthreads();

    float rm0 = -INFINITY, rs0 = 0.f, rm1 = -INFINITY, rs1 = 0.f;

    for (int nt = 0; nt < tiles; nt++) {
        const int n0 = nbeg + nt * 128;
        const __nv_bfloat16* bb = g_bankb + (size_t)n0 * Dn;

        auto issueB = [&](int c, uint32_t buf) {
#pragma unroll
            for (int u = tid; u < 512; u += 256) {  // 128 rows x 4 16B-segs
                int r = u >> 2, seg = u & 3;
                cp16(buf + r * (BSTRIDE * 2) + seg * 16, bb + (size_t)r * Dn + c * KC + seg * 8);
            }
        };
#pragma unroll
        for (int p = 0; p < 4; p++) { issueB(p, sB + p * BSTG_BYTES); cp_commit(); }

        float acc[16][4];
#pragma unroll
        for (int q = 0; q < 16; q++)
#pragma unroll
            for (int j = 0; j < 4; j++) acc[q][j] = 0.f;

        for (int kc = 0; kc < NKCH; kc++) {
            cp_wait3();
            __syncthreads();
            int nx = kc + 4;
            if (nx < NKCH) issueB(nx, sB + (nx % BSTAGES) * BSTG_BYTES);
            cp_commit();   // real or empty group: keeps wait_group 3 invariant

            // A fragments for this warp's 16 rows at k = kc*32
            uint32_t a[2][4];
            {
                uint32_t aaddr = sA + (warp * 16 + (lane & 15)) * (ASTRIDE * 2)
                               + (kc * KC + ((lane >> 4) << 3)) * 2;
                ldsm_x4(a[0][0], a[0][1], a[0][2], a[0][3], aaddr);
                ldsm_x4(a[1][0], a[1][1], a[1][2], a[1][3], aaddr + 32);
            }
            const uint32_t bufb = sB + (kc % BSTAGES) * BSTG_BYTES;
#pragma unroll
            for (int q = 0; q < 16; q++) {
                uint32_t baddr = bufb + (q * 8 + (lane & 7)) * (BSTRIDE * 2)
                               + ((((lane >> 3) & 3) << 3) << 1);
                uint32_t b0, b1, b2, b3;
                ldsm_x4t(b0, b1, b2, b3, baddr);
                mma16816(acc[q], a[0], b0, b1);
                mma16816(acc[q], a[1], b2, b3);
            }
        }
        __syncthreads();  // before next tile's prefetch reuses buffers

        // ---- online LSE fold (rows lane>>2 and +8 of this warp's 16) ----
        if (n0 + 128 > nend) {
            int cb = n0 + (lane & 3) * 2;
#pragma unroll
            for (int q = 0; q < 16; q++) {
                int c = cb + q * 8;
                if (c >= nend)     { acc[q][0] = -INFINITY; acc[q][2] = -INFINITY; }
                if (c + 1 >= nend) { acc[q][1] = -INFINITY; acc[q][3] = -INFINITY; }
            }
        }
        float m0l = -INFINITY, m1l = -INFINITY;
#pragma unroll
        for (int q = 0; q < 16; q++) {
            m0l = fmaxf(m0l, fmaxf(acc[q][0], acc[q][1]));
            m1l = fmaxf(m1l, fmaxf(acc[q][2], acc[q][3]));
        }
        m0l = fmaxf(m0l, __shfl_xor_sync(0xffffffffu, m0l, 1));
        m0l = fmaxf(m0l, __shfl_xor_sync(0xffffffffu, m0l, 2));
        m1l = fmaxf(m1l, __shfl_xor_sync(0xffffffffu, m1l, 1));
        m1l = fmaxf(m1l, __shfl_xor_sync(0xffffffffu, m1l, 2));
        float nm0 = fmaxf(fmaxf(rm0, m0l), -1e30f);
        float nm1 = fmaxf(fmaxf(rm1, m1l), -1e30f);
        float s0 = 0.f, s1 = 0.f;
#pragma unroll
        for (int q = 0; q < 16; q++) {
            s0 += __expf(acc[q][0] - nm0) + __expf(acc[q][1] - nm0);
            s1 += __expf(acc[q][2] - nm1) + __expf(acc[q][3] - nm1);
        }
        s0 += __shfl_xor_sync(0xffffffffu, s0, 1);
        s0 += __shfl_xor_sync(0xffffffffu, s0, 2);
        s1 += __shfl_xor_sync(0xffffffffu, s1, 1);
        s1 += __shfl_xor_sync(0xffffffffu, s1, 2);
        rs0 = rs0 * __expf(rm0 - nm0) + s0; rm0 = nm0;
        rs1 = rs1 * __expf(rm1 - nm1) + s1; rm1 = nm1;
    }

    if ((lane & 3) == 0) {
        int r0 = m0 + warp * 16 + (lane >> 2);
        int base = (dir * NCHUNKS + chunk) * BT;
        g_pm[base + r0] = rm0;     g_ps[base + r0] = rs0;
        g_pm[base + r0 + 8] = rm1; g_ps[base + r0 + 8] = rs1;
    }
}

// ------------------------------------------------------------------
// 5) combine N-chunk partials into lse per row
// ------------------------------------------------------------------
__global__ void combine_kernel() {
    int idx = blockIdx.x * blockDim.x + threadIdx.x;
    if (idx >= 2 * BT) return;
    int dir = idx / BT, r = idx % BT;
    if (r >= g_S) return;
    float M = -INFINITY;
#pragma unroll
    for (int c = 0; c < NCHUNKS; c++)
        M = fmaxf(M, g_pm[(dir * NCHUNKS + c) * BT + r]);
    float s = 0.f;
#pragma unroll
    for (int c = 0; c < NCHUNKS; c++) {
        float mm = g_pm[(dir * NCHUNKS + c) * BT + r];
        float ss = g_ps[(dir * NCHUNKS + c) * BT + r];
        if (ss > 0.f) s += ss * __expf(mm - M);
    }
    g_lse[dir * BT + r] = M + logf(s);
}

// ------------------------------------------------------------------
// 6) final reduction -> out[0]=fw_loss, out[1]=bw_loss
// ------------------------------------------------------------------
__global__ void reduce_kernel(float* __restrict__ out) {
    __shared__ double sh[256][2];
    int tid = threadIdx.x;
    int S = g_S;
    double a0 = 0.0, a1 = 0.0;
    for (int r = tid; r < S; r += 256) {
        double w = (double)g_invL[g_rowbatch[r]];
        a0 += (double)(g_lse[r]      - g_diag[r])      * w;
        a1 += (double)(g_lse[BT + r] - g_diag[BT + r]) * w;
    }
    sh[tid][0] = a0; sh[tid][1] = a1;
    __syncthreads();
    for (int o = 128; o >= 1; o >>= 1) {
        if (tid < o) { sh[tid][0] += sh[tid + o][0]; sh[tid][1] += sh[tid + o][1]; }
        __syncthreads();
    }
    if (tid == 0) {
        out[0] = (float)(sh[0][0] / (double)Bn);
        out[1] = (float)(sh[0][1] / (double)Bn);
    }
}

// ------------------------------------------------------------------
extern "C" void kernel_launch(void* const* d_in, const int* in_sizes, int n_in,
                              void* d_out, int out_size) {
    const float* feats    = (const float*)d_in[0];
    const float* hidden   = (const float*)d_in[1];
    const int*   seq_lens = (const int*)d_in[2];
    float* out = (float*)d_out;

    cudaFuncSetAttribute(lse_kernel, cudaFuncAttributeMaxDynamicSharedMemorySize, DYN_BYTES);

    setup_kernel<<<1, 256>>>(seq_lens);
    hidcvt_kernel<<<BT, 256>>>(hidden);
    bankcvt_kernel<<<TOTPAD, 128>>>(feats);
    diag_kernel<<<dim3(BT / 8, 2), 256>>>(hidden, feats);
    lse_kernel<<<dim3(MT_MAX, NCHUNKS, 2), 256, DYN_BYTES>>>();
    combine_kernel<<<(2 * BT + 255) / 256, 256>>>();
    reduce_kernel<<<1, 256>>>(out);
    (void)in_sizes; (void)n_in; (void)out_size;
}